// round 2
// baseline (speedup 1.0000x reference)
#include <cuda_runtime.h>
#include <math.h>

// ---------------------------------------------------------------------------
// Fused APSGNN packet-router model, FP32 SIMT baseline with f32x2 packed FMA.
//   h = LN( key@Wk + aux@Wa + 0.1*res@Wr + (bk+ba+0.1*br) )
//   h = LN(GELU(h@Wb0+bb0)); h = LN(GELU(h@Wb1+bb1))
//   logits = role==0 ? h@Ww+bw : h@Wq+bq ;  addr = h@Wad+bad
// Output layout: [logits (N*1024) | h (N*256) | addr (N*64)], fp32.
// ---------------------------------------------------------------------------

namespace {

constexpr int KD = 128, DM = 256, HD = 256, NC = 1024, AD = 64;
constexpr int RB  = 64;    // rows per block
constexpr int TPB = 256;   // threads per block
constexpr int KC  = 16;    // K chunk
constexpr float SCALE = 0.1f;

constexpr int SM_A_SZ = KC * RB;          // 1024 floats
constexpr int SM_B_SZ = KC * HD;          // 4096 floats
constexpr int SM_H_SZ = HD * (RB + 1);    // 16640 floats (transposed h, padded)
constexpr int SM_BIAS = HD;               // 256
constexpr int SM_ROLE = RB;               // 64 (ints stored in float slots)
constexpr int SMEM_FLOATS = SM_A_SZ + SM_B_SZ + SM_H_SZ + SM_BIAS + SM_ROLE;
constexpr size_t SMEM_BYTES = (size_t)SMEM_FLOATS * 4;

__device__ __forceinline__ unsigned long long pack2(float lo, float hi) {
    unsigned long long r;
    asm("mov.b64 %0, {%1, %2};" : "=l"(r) : "f"(lo), "f"(hi));
    return r;
}
__device__ __forceinline__ void fma2(unsigned long long& acc,
                                     unsigned long long a, unsigned long long b) {
    asm("fma.rn.f32x2 %0, %1, %2, %0;" : "+l"(acc) : "l"(a), "l"(b));
}
__device__ __forceinline__ float2 unpack2(unsigned long long v) {
    float lo, hi;
    asm("mov.b64 {%0, %1}, %2;" : "=f"(lo), "=f"(hi) : "l"(v));
    return make_float2(lo, hi);
}
__device__ __forceinline__ float gelu_exact(float x) {
    return 0.5f * x * (1.0f + erff(x * 0.70710678118654752440f));
}

} // namespace

__global__ void __launch_bounds__(TPB, 2)
apsgnn_fused_kernel(const float* __restrict__ key,
                    const float* __restrict__ aux,
                    const float* __restrict__ res,
                    const int*   __restrict__ role,
                    const float* __restrict__ Wk,  const float* __restrict__ bk,
                    const float* __restrict__ Wa,  const float* __restrict__ ba,
                    const float* __restrict__ Wr,  const float* __restrict__ br,
                    const float* __restrict__ g_in,const float* __restrict__ b_in,
                    const float* __restrict__ Wb0, const float* __restrict__ bb0,
                    const float* __restrict__ g0,  const float* __restrict__ beta0,
                    const float* __restrict__ Wb1, const float* __restrict__ bb1,
                    const float* __restrict__ g1,  const float* __restrict__ beta1,
                    const float* __restrict__ Ww,  const float* __restrict__ bw,
                    const float* __restrict__ Wq,  const float* __restrict__ bq,
                    const float* __restrict__ Wad, const float* __restrict__ bad,
                    float* __restrict__ out_logits,
                    float* __restrict__ out_h,
                    float* __restrict__ out_addr)
{
    extern __shared__ float smem[];
    float (*sA)[RB]     = (float (*)[RB])(smem);
    float (*sB)[HD]     = (float (*)[HD])(smem + SM_A_SZ);
    float (*hb)[RB + 1] = (float (*)[RB + 1])(smem + SM_A_SZ + SM_B_SZ);
    float* sBias        = smem + SM_A_SZ + SM_B_SZ + SM_H_SZ;
    int*   sRole        = (int*)(smem + SM_A_SZ + SM_B_SZ + SM_H_SZ + SM_BIAS);

    const int tid  = threadIdx.x;
    const int row0 = blockIdx.x * RB;
    const int cg   = tid & 31;   // column group (also lane id)
    const int rg   = tid >> 5;   // row group (warp id)
    const int lane = cg;

    if (tid < RB) sRole[tid] = role[row0 + tid];
    // combined input bias: bk + ba + 0.1*br
    sBias[tid] = bk[tid] + ba[tid] + SCALE * br[tid];

    // 8 rows x 8 cols per thread; columns packed as f32x2 pairs -> [8][4]
    unsigned long long acc[8][4];

    auto zeroAcc = [&]() {
        #pragma unroll
        for (int r = 0; r < 8; ++r)
            #pragma unroll
            for (int p = 0; p < 4; ++p) acc[r][p] = 0ull;
    };

    // cols for pair p: p=0 -> cg*4, p=1 -> cg*4+2, p=2 -> 128+cg*4, p=3 -> 128+cg*4+2
    auto colOfPair = [&](int p) {
        return ((p >> 1) ? 128 : 0) + cg * 4 + ((p & 1) << 1);
    };

    // A rows for this thread are contiguous (sA row layout is [k][r], r contiguous):
    // vectorize the 8 broadcast reads into two float4 loads (32B-aligned by
    // construction: row stride 256B, rg*8*4 = 32B multiple).
    auto innerFMA = [&](const float* __restrict__ arow, const float* __restrict__ brow) {
        unsigned long long b0 = *(const unsigned long long*)(brow + cg * 4);
        unsigned long long b1 = *(const unsigned long long*)(brow + cg * 4 + 2);
        unsigned long long b2 = *(const unsigned long long*)(brow + 128 + cg * 4);
        unsigned long long b3 = *(const unsigned long long*)(brow + 128 + cg * 4 + 2);
        const float4 a_lo = *(const float4*)(arow + rg * 8);
        const float4 a_hi = *(const float4*)(arow + rg * 8 + 4);
        float a_s[8] = {a_lo.x, a_lo.y, a_lo.z, a_lo.w,
                        a_hi.x, a_hi.y, a_hi.z, a_hi.w};
        #pragma unroll
        for (int r = 0; r < 8; ++r) {
            unsigned long long a2 = pack2(a_s[r], a_s[r]);
            fma2(acc[r][0], a2, b0);
            fma2(acc[r][1], a2, b1);
            fma2(acc[r][2], a2, b2);
            fma2(acc[r][3], a2, b3);
        }
    };

    // GEMM chunk with A from global memory (rows row0..row0+63), W cols [colOff, colOff+256)
    auto gemmGlobal = [&](const float* __restrict__ A, int lda, float ascale,
                          const float* __restrict__ W, int ldw, int colOff, int K) {
        for (int k0 = 0; k0 < K; k0 += KC) {
            __syncthreads();
            {   // stage A chunk transposed: sA[k][r]; 256 float4 = 1 per thread
                int r  = tid >> 2;
                int kq = (tid & 3) << 2;
                const float4 v = *(const float4*)(A + (size_t)(row0 + r) * lda + k0 + kq);
                sA[kq + 0][r] = v.x * ascale;
                sA[kq + 1][r] = v.y * ascale;
                sA[kq + 2][r] = v.z * ascale;
                sA[kq + 3][r] = v.w * ascale;
            }
            #pragma unroll
            for (int i = 0; i < KC; ++i)
                sB[i][tid] = W[(size_t)(k0 + i) * ldw + colOff + tid];
            __syncthreads();
            #pragma unroll
            for (int k = 0; k < KC; ++k)
                innerFMA(&sA[k][0], &sB[k][0]);
        }
    };

    // GEMM with A = hb (transposed h in smem), K = HD
    auto gemmHidden = [&](const float* __restrict__ W, int ldw, int colOff) {
        for (int k0 = 0; k0 < HD; k0 += KC) {
            __syncthreads();
            #pragma unroll
            for (int i = 0; i < KC; ++i)
                sB[i][tid] = W[(size_t)(k0 + i) * ldw + colOff + tid];
            __syncthreads();
            #pragma unroll
            for (int k = 0; k < KC; ++k) {
                // hb row: r contiguous with stride 1, same vector trick applies,
                // but row stride is 65 floats (4B-aligned only) -> keep scalar
                // broadcast loads here (they are bank-conflict-free broadcasts).
                const float* arow = &hb[k0 + k][0];
                const float* brow = &sB[k][0];
                unsigned long long b0 = *(const unsigned long long*)(brow + cg * 4);
                unsigned long long b1 = *(const unsigned long long*)(brow + cg * 4 + 2);
                unsigned long long b2 = *(const unsigned long long*)(brow + 128 + cg * 4);
                unsigned long long b3 = *(const unsigned long long*)(brow + 128 + cg * 4 + 2);
                #pragma unroll
                for (int r = 0; r < 8; ++r) {
                    float a = arow[rg * 8 + r];
                    unsigned long long a2 = pack2(a, a);
                    fma2(acc[r][0], a2, b0);
                    fma2(acc[r][1], a2, b1);
                    fma2(acc[r][2], a2, b2);
                    fma2(acc[r][3], a2, b3);
                }
            }
        }
    };

    // per-row LayerNorm over 256 cols of hb; warp rg handles rows rg*8..rg*8+7
    auto layernorm = [&](const float* __restrict__ g, const float* __restrict__ b) {
        #pragma unroll
        for (int rr = 0; rr < 8; ++rr) {
            int r = rg * 8 + rr;
            float s = 0.f;
            #pragma unroll
            for (int i = 0; i < 8; ++i) s += hb[lane + i * 32][r];
            #pragma unroll
            for (int o = 16; o; o >>= 1) s += __shfl_xor_sync(0xffffffffu, s, o);
            float mean = s * (1.0f / HD);
            float var = 0.f;
            #pragma unroll
            for (int i = 0; i < 8; ++i) {
                float d = hb[lane + i * 32][r] - mean;
                var += d * d;
            }
            #pragma unroll
            for (int o = 16; o; o >>= 1) var += __shfl_xor_sync(0xffffffffu, var, o);
            float rstd = rsqrtf(var * (1.0f / HD) + 1e-5f);
            #pragma unroll
            for (int i = 0; i < 8; ++i) {
                int c = lane + i * 32;
                hb[c][r] = (hb[c][r] - mean) * rstd * g[c] + b[c];
            }
        }
    };

    // ---- Phase 1: input projections -> h0 ----
    zeroAcc();
    gemmGlobal(key, KD, 1.0f,  Wk, HD, 0, KD);
    gemmGlobal(aux, DM, 1.0f,  Wa, HD, 0, DM);
    gemmGlobal(res, DM, SCALE, Wr, HD, 0, DM);
    // write acc (+bias) into hb (disjoint elements; no sync needed before writes)
    #pragma unroll
    for (int r = 0; r < 8; ++r) {
        int R = rg * 8 + r;
        #pragma unroll
        for (int p = 0; p < 4; ++p) {
            float2 v = unpack2(acc[r][p]);
            int c = colOfPair(p);
            hb[c][R]     = v.x + sBias[c];
            hb[c + 1][R] = v.y + sBias[c + 1];
        }
    }
    __syncthreads();
    layernorm(g_in, b_in);
    __syncthreads();

    // ---- Phase 2 & 3: backbone layers ----
    {
        const float* Wb[2]  = {Wb0, Wb1};
        const float* bb[2]  = {bb0, bb1};
        const float* gg[2]  = {g0, g1};
        const float* bbe[2] = {beta0, beta1};
        for (int L = 0; L < 2; ++L) {
            zeroAcc();
            gemmHidden(Wb[L], HD, 0);
            __syncthreads();   // everyone done reading hb before overwriting
            #pragma unroll
            for (int r = 0; r < 8; ++r) {
                int R = rg * 8 + r;
                #pragma unroll
                for (int p = 0; p < 4; ++p) {
                    float2 v = unpack2(acc[r][p]);
                    int c = colOfPair(p);
                    hb[c][R]     = gelu_exact(v.x + bb[L][c]);
                    hb[c + 1][R] = gelu_exact(v.y + bb[L][c + 1]);
                }
            }
            __syncthreads();
            layernorm(gg[L], bbe[L]);
            __syncthreads();
        }
    }

    // ---- h output ----
    for (int idx = tid; idx < RB * HD; idx += TPB) {
        int r = idx >> 8;          // /256
        int c = idx & (HD - 1);
        out_h[(size_t)(row0 + r) * HD + c] = hb[c][r];
    }

    // ---- address head (small: 64 cols) ----
    for (int idx = tid; idx < RB * AD; idx += TPB) {
        int r = idx >> 6;
        int c = idx & (AD - 1);
        float s = bad[c];
        #pragma unroll 8
        for (int k = 0; k < HD; ++k) s = fmaf(hb[k][r], Wad[k * AD + c], s);
        out_addr[(size_t)(row0 + r) * AD + c] = s;
    }

    // ---- role-dispatched logits head: 4 col tiles x {writer pass, query pass} ----
    for (int ct = 0; ct < 4; ++ct) {
        int co = ct * 256;

        zeroAcc();
        gemmHidden(Ww, NC, co);
        #pragma unroll
        for (int r = 0; r < 8; ++r) {
            int R = rg * 8 + r;
            if (sRole[R] == 0) {
                float* orow = out_logits + (size_t)(row0 + R) * NC + co;
                #pragma unroll
                for (int p = 0; p < 4; ++p) {
                    float2 v = unpack2(acc[r][p]);
                    int c = colOfPair(p);
                    orow[c]     = v.x + bw[co + c];
                    orow[c + 1] = v.y + bw[co + c + 1];
                }
            }
        }

        zeroAcc();
        gemmHidden(Wq, NC, co);
        #pragma unroll
        for (int r = 0; r < 8; ++r) {
            int R = rg * 8 + r;
            if (sRole[R] != 0) {
                float* orow = out_logits + (size_t)(row0 + R) * NC + co;
                #pragma unroll
                for (int p = 0; p < 4; ++p) {
                    float2 v = unpack2(acc[r][p]);
                    int c = colOfPair(p);
                    orow[c]     = v.x + bq[co + c];
                    orow[c + 1] = v.y + bq[co + c + 1];
                }
            }
        }
    }
}

extern "C" void kernel_launch(void* const* d_in, const int* in_sizes, int n_in,
                              void* d_out, int out_size) {
    const float* key   = (const float*)d_in[0];
    const float* aux   = (const float*)d_in[1];
    const float* res   = (const float*)d_in[2];
    const int*   role  = (const int*)  d_in[3];
    const float* Wk    = (const float*)d_in[4];
    const float* bk    = (const float*)d_in[5];
    const float* Wa    = (const float*)d_in[6];
    const float* ba    = (const float*)d_in[7];
    const float* Wr    = (const float*)d_in[8];
    const float* br    = (const float*)d_in[9];
    const float* g_in  = (const float*)d_in[10];
    const float* b_in  = (const float*)d_in[11];
    const float* Wb0   = (const float*)d_in[12];
    const float* bb0   = (const float*)d_in[13];
    const float* g0    = (const float*)d_in[14];
    const float* beta0 = (const float*)d_in[15];
    const float* Wb1   = (const float*)d_in[16];
    const float* bb1   = (const float*)d_in[17];
    const float* g1    = (const float*)d_in[18];
    const float* beta1 = (const float*)d_in[19];
    const float* Ww    = (const float*)d_in[20];
    const float* bw    = (const float*)d_in[21];
    const float* Wq    = (const float*)d_in[22];
    const float* bq    = (const float*)d_in[23];
    const float* Wad   = (const float*)d_in[24];
    const float* bad   = (const float*)d_in[25];

    const int N = in_sizes[3];   // role has one entry per packet

    float* out        = (float*)d_out;
    float* out_logits = out;
    float* out_h      = out + (size_t)N * NC;
    float* out_addr   = out + (size_t)N * (NC + HD);

    cudaFuncSetAttribute(apsgnn_fused_kernel,
                         cudaFuncAttributeMaxDynamicSharedMemorySize,
                         (int)SMEM_BYTES);

    dim3 grid(N / RB);
    apsgnn_fused_kernel<<<grid, TPB, SMEM_BYTES>>>(
        key, aux, res, role,
        Wk, bk, Wa, ba, Wr, br, g_in, b_in,
        Wb0, bb0, g0, beta0, Wb1, bb1, g1, beta1,
        Ww, bw, Wq, bq, Wad, bad,
        out_logits, out_h, out_addr);
}

// round 7
// speedup vs baseline: 2.1653x; 2.1653x over previous
#include <cuda_runtime.h>
#include <cuda_bf16.h>
#include <stdint.h>
#include <math.h>

// Fused APSGNN model on tensor cores (mma.sync m16n8k16 bf16, 3xBF16 split).
// Output: [logits N*1024 | h N*256 | addr N*64], fp32.

namespace {

constexpr int HD = 256, NC = 1024, AD = 64;
constexpr int RB = 128, TPB = 512;
constexpr int KS_IN = 40, KS_H = 16;

constexpr int WIN_SS = KS_IN * 32 * 64;
constexpr int WB_SS  = KS_H * 32 * 64;
constexpr int WH_SS  = KS_H * 128 * 64;
constexpr int WAD_SS = KS_H * 8 * 64;

constexpr int OFF_SA_HI = 0;
constexpr int OFF_SA_LO = OFF_SA_HI + 65536;
constexpr int OFF_SB    = OFF_SA_LO + 65536;
constexpr int OFF_SAIN  = OFF_SB + 32768;
constexpr int OFF_LN    = OFF_SAIN + 16384;
constexpr int OFF_BIAS  = OFF_LN + 2048;
constexpr int OFF_ROLE  = OFF_BIAS + 1024;
constexpr int SMEM_BYTES = OFF_ROLE + 512;

__device__ uint32_t g_Win[2 * WIN_SS];
__device__ uint32_t g_Wb0[2 * WB_SS];
__device__ uint32_t g_Wb1[2 * WB_SS];
__device__ uint32_t g_Ww [2 * WH_SS];
__device__ uint32_t g_Wq [2 * WH_SS];
__device__ uint32_t g_Wad[2 * WAD_SS];

__device__ __forceinline__ void mma_bf16(float (&d)[4], uint32_t a0, uint32_t a1,
                                         uint32_t a2, uint32_t a3,
                                         uint32_t b0, uint32_t b1) {
    asm volatile(
        "mma.sync.aligned.m16n8k16.row.col.f32.bf16.bf16.f32 "
        "{%0,%1,%2,%3}, {%4,%5,%6,%7}, {%8,%9}, {%0,%1,%2,%3};"
        : "+f"(d[0]), "+f"(d[1]), "+f"(d[2]), "+f"(d[3])
        : "r"(a0), "r"(a1), "r"(a2), "r"(a3), "r"(b0), "r"(b1));
}

__device__ __forceinline__ void split_pack(float e0, float e1,
                                           uint32_t& hiw, uint32_t& low) {
    __nv_bfloat16 h0 = __float2bfloat16(e0), h1 = __float2bfloat16(e1);
    hiw = ((uint32_t)__bfloat16_as_ushort(h1) << 16) | __bfloat16_as_ushort(h0);
    __nv_bfloat16 l0 = __float2bfloat16(e0 - __bfloat162float(h0));
    __nv_bfloat16 l1 = __float2bfloat16(e1 - __bfloat162float(h1));
    low = ((uint32_t)__bfloat16_as_ushort(l1) << 16) | __bfloat16_as_ushort(l0);
}

__device__ __forceinline__ float gelu_exact(float x) {
    return 0.5f * x * (1.0f + erff(x * 0.70710678118654752440f));
}

} // namespace

// Pack W[K][N] (fp32 row-major, scaled) into fragment order + lo residual.
__global__ void pack_weight_kernel(const float* __restrict__ W, int K, int N,
                                   float scale, uint32_t* __restrict__ dst,
                                   int ksBase, int NTp, int splitStride) {
    int w = blockIdx.x * blockDim.x + threadIdx.x;
    if (w >= (K / 16) * (N / 8) * 64) return;
    int w2 = w & 1, lane = (w >> 1) & 31;
    int ng = (w >> 6) % (N / 8), ks = (w >> 6) / (N / 8);
    int k = ks * 16 + (lane & 3) * 2 + w2 * 8;
    int n = ng * 8 + (lane >> 2);
    uint32_t hw, lw;
    split_pack(W[(size_t)k * N + n] * scale, W[(size_t)(k + 1) * N + n] * scale, hw, lw);
    size_t o = ((size_t)(ks + ksBase) * NTp + ng) * 64 + lane * 2 + w2;
    dst[o] = hw;
    dst[o + splitStride] = lw;
}

__global__ void __launch_bounds__(TPB, 1)
apsgnn_mma_kernel(const float* __restrict__ key, const float* __restrict__ aux,
                  const float* __restrict__ res, const int* __restrict__ role,
                  const float* __restrict__ bk, const float* __restrict__ ba,
                  const float* __restrict__ br,
                  const float* __restrict__ g_in, const float* __restrict__ b_in,
                  const float* __restrict__ bb0, const float* __restrict__ g0,
                  const float* __restrict__ beta0,
                  const float* __restrict__ bb1, const float* __restrict__ g1,
                  const float* __restrict__ beta1,
                  const float* __restrict__ bw, const float* __restrict__ bq,
                  const float* __restrict__ bad,
                  float* __restrict__ out_logits, float* __restrict__ out_h,
                  float* __restrict__ out_addr)
{
    extern __shared__ unsigned char sm[];
    uint32_t* sAhi  = (uint32_t*)(sm + OFF_SA_HI);
    uint32_t* sAlo  = (uint32_t*)(sm + OFF_SA_LO);
    uint32_t* sB    = (uint32_t*)(sm + OFF_SB);
    uint32_t* sAin  = (uint32_t*)(sm + OFF_SAIN);
    float2*   lnb   = (float2*)  (sm + OFF_LN);
    float*    sBias = (float*)   (sm + OFF_BIAS);
    int*      sRole = (int*)     (sm + OFF_ROLE);

    const int tid  = threadIdx.x;
    const int lane = tid & 31;
    const int warp = tid >> 5;
    const int mt   = warp >> 1;
    const int cg   = warp & 1;
    const int row0 = blockIdx.x * RB;

    if (tid < RB) sRole[tid] = role[row0 + tid];
    if (tid < HD) sBias[tid] = bk[tid] + ba[tid] + 0.1f * br[tid];

    const int qrow = lane >> 2;
    const int cb   = (lane & 3) * 2;
    const int r0   = mt * 16 + qrow;
    const int r1   = r0 + 8;

    float d[16][4];

    auto zeroD = [&]() {
        #pragma unroll
        for (int nt = 0; nt < 16; ++nt)
            #pragma unroll
            for (int j = 0; j < 4; ++j) d[nt][j] = 0.f;
    };

    auto stageB = [&](const uint32_t* __restrict__ gW, int splitStride,
                      int ks, int NTp, int ng0, int nwords, int buf) {
        const uint32_t* srcH = gW + ((size_t)ks * NTp + ng0) * 64;
        uint32_t* dstH = sB + buf * 4096;
        int w = tid * 4;
        if (w < nwords) {
            *(uint4*)(dstH + w)        = *(const uint4*)(srcH + w);
            *(uint4*)(dstH + 2048 + w) = *(const uint4*)(srcH + splitStride + w);
        }
    };

    auto stageAin = [&](int ks, int buf) {
        #pragma unroll
        for (int rep = 0; rep < 2; ++rep) {
            int w = tid + rep * 512;
            int i  = w & 3;
            int ln = (w >> 2) & 31;
            int m  = w >> 7;
            int r  = m * 16 + (ln >> 2) + (i & 1) * 8;
            int kg = ks * 16 + (ln & 3) * 2 + (i >> 1) * 8;
            const float* src; int ld; int col;
            if (kg < 128)      { src = key; ld = 128; col = kg; }
            else if (kg < 384) { src = aux; ld = 256; col = kg - 128; }
            else               { src = res; ld = 256; col = kg - 384; }
            float2 v = *(const float2*)(src + (size_t)(row0 + r) * ld + col);
            uint32_t hw, lw;
            split_pack(v.x, v.y, hw, lw);
            sAin[buf * 2048 + w]        = hw;
            sAin[buf * 2048 + 1024 + w] = lw;
        }
    };

    auto mmaStep = [&](const uint32_t* aHp, const uint32_t* aLp, int buf,
                       int ntCount, int ngBase) {
        uint4 Ah = *(const uint4*)aHp;
        uint4 Al = *(const uint4*)aLp;
        const uint32_t* bH = sB + buf * 4096;
        const uint32_t* bL = bH + 2048;
        #pragma unroll
        for (int nt = 0; nt < 16; ++nt) {
            if (nt >= ntCount) break;
            int ng = ngBase + nt;
            uint2 bh = *(const uint2*)(bH + (ng * 32 + lane) * 2);
            uint2 bl = *(const uint2*)(bL + (ng * 32 + lane) * 2);
            mma_bf16(d[nt], Ah.x, Ah.y, Ah.z, Ah.w, bh.x, bh.y);
            mma_bf16(d[nt], Ah.x, Ah.y, Ah.z, Ah.w, bl.x, bl.y);
            mma_bf16(d[nt], Al.x, Al.y, Al.z, Al.w, bh.x, bh.y);
        }
    };

    auto layernormD = [&](const float* __restrict__ g, const float* __restrict__ be) {
        float s0 = 0.f, q0 = 0.f, s1 = 0.f, q1 = 0.f;
        #pragma unroll
        for (int nt = 0; nt < 16; ++nt) {
            s0 += d[nt][0] + d[nt][1];
            q0 += d[nt][0] * d[nt][0] + d[nt][1] * d[nt][1];
            s1 += d[nt][2] + d[nt][3];
            q1 += d[nt][2] * d[nt][2] + d[nt][3] * d[nt][3];
        }
        #pragma unroll
        for (int off = 1; off <= 2; off <<= 1) {
            s0 += __shfl_xor_sync(0xffffffffu, s0, off);
            q0 += __shfl_xor_sync(0xffffffffu, q0, off);
            s1 += __shfl_xor_sync(0xffffffffu, s1, off);
            q1 += __shfl_xor_sync(0xffffffffu, q1, off);
        }
        if ((lane & 3) == 0) {
            lnb[r0 * 2 + cg] = make_float2(s0, q0);
            lnb[r1 * 2 + cg] = make_float2(s1, q1);
        }
        __syncthreads();
        float2 p0a = lnb[r0 * 2], p0b = lnb[r0 * 2 + 1];
        float2 p1a = lnb[r1 * 2], p1b = lnb[r1 * 2 + 1];
        float mean0 = (p0a.x + p0b.x) * (1.f / HD);
        float rstd0 = rsqrtf((p0a.y + p0b.y) * (1.f / HD) - mean0 * mean0 + 1e-5f);
        float mean1 = (p1a.x + p1b.x) * (1.f / HD);
        float rstd1 = rsqrtf((p1a.y + p1b.y) * (1.f / HD) - mean1 * mean1 + 1e-5f);
        #pragma unroll
        for (int nt = 0; nt < 16; ++nt) {
            int c = cg * 128 + nt * 8 + cb;
            float2 gv = *(const float2*)(g + c);
            float2 bv = *(const float2*)(be + c);
            d[nt][0] = (d[nt][0] - mean0) * rstd0 * gv.x + bv.x;
            d[nt][1] = (d[nt][1] - mean0) * rstd0 * gv.y + bv.y;
            d[nt][2] = (d[nt][2] - mean1) * rstd1 * gv.x + bv.x;
            d[nt][3] = (d[nt][3] - mean1) * rstd1 * gv.y + bv.y;
        }
    };

    auto writeSA = [&]() {
        #pragma unroll
        for (int nt = 0; nt < 16; ++nt) {
            int ks2 = cg * 8 + (nt >> 1);
            int idx = ((mt * 16 + ks2) * 32 + lane) * 4 + (nt & 1) * 2;
            uint32_t hw, lw;
            split_pack(d[nt][0], d[nt][1], hw, lw);
            sAhi[idx] = hw;  sAlo[idx] = lw;
            split_pack(d[nt][2], d[nt][3], hw, lw);
            sAhi[idx + 1] = hw;  sAlo[idx + 1] = lw;
        }
    };

    // ---- Stage 1: input projections (K=640) ----
    zeroD();
    stageAin(0, 0);
    stageB(g_Win, WIN_SS, 0, 32, 0, 2048, 0);
    __syncthreads();
    for (int ks = 0; ks < KS_IN; ++ks) {
        int buf = ks & 1;
        if (ks + 1 < KS_IN) {
            stageAin(ks + 1, buf ^ 1);
            stageB(g_Win, WIN_SS, ks + 1, 32, 0, 2048, buf ^ 1);
        }
        mmaStep(sAin + buf * 2048 + (mt * 32 + lane) * 4,
                sAin + buf * 2048 + 1024 + (mt * 32 + lane) * 4, buf, 16, cg * 16);
        __syncthreads();
    }
    #pragma unroll
    for (int nt = 0; nt < 16; ++nt) {
        int c = cg * 128 + nt * 8 + cb;
        d[nt][0] += sBias[c];   d[nt][1] += sBias[c + 1];
        d[nt][2] += sBias[c];   d[nt][3] += sBias[c + 1];
    }
    layernormD(g_in, b_in);
    writeSA();
    __syncthreads();

    // ---- Stages 2-3: backbone ----
    for (int L = 0; L < 2; ++L) {
        const uint32_t* gW = (L == 0) ? g_Wb0 : g_Wb1;
        const float* bbL = (L == 0) ? bb0 : bb1;
        const float* gL  = (L == 0) ? g0 : g1;
        const float* beL = (L == 0) ? beta0 : beta1;
        zeroD();
        stageB(gW, WB_SS, 0, 32, 0, 2048, 0);
        __syncthreads();
        for (int ks = 0; ks < KS_H; ++ks) {
            int buf = ks & 1;
            if (ks + 1 < KS_H) stageB(gW, WB_SS, ks + 1, 32, 0, 2048, buf ^ 1);
            mmaStep(sAhi + ((mt * 16 + ks) * 32 + lane) * 4,
                    sAlo + ((mt * 16 + ks) * 32 + lane) * 4, buf, 16, cg * 16);
            __syncthreads();
        }
        #pragma unroll
        for (int nt = 0; nt < 16; ++nt) {
            int c = cg * 128 + nt * 8 + cb;
            float2 bv = *(const float2*)(bbL + c);
            d[nt][0] = gelu_exact(d[nt][0] + bv.x);
            d[nt][1] = gelu_exact(d[nt][1] + bv.y);
            d[nt][2] = gelu_exact(d[nt][2] + bv.x);
            d[nt][3] = gelu_exact(d[nt][3] + bv.y);
        }
        layernormD(gL, beL);
        writeSA();
        if (L == 1) {
            #pragma unroll
            for (int nt = 0; nt < 16; ++nt) {
                int c = cg * 128 + nt * 8 + cb;
                *(float2*)(out_h + (size_t)(row0 + r0) * HD + c) = make_float2(d[nt][0], d[nt][1]);
                *(float2*)(out_h + (size_t)(row0 + r1) * HD + c) = make_float2(d[nt][2], d[nt][3]);
            }
        }
        __syncthreads();
    }

    // ---- Stage 4: logits heads ----
    const int role0 = sRole[r0];
    const int role1 = sRole[r1];
    for (int cc = 0; cc < 4; ++cc) {
        for (int head = 0; head < 2; ++head) {
            const uint32_t* gW = head ? g_Wq : g_Ww;
            const float* bias  = head ? bq : bw;
            zeroD();
            stageB(gW, WH_SS, 0, 128, cc * 32, 2048, 0);
            __syncthreads();
            for (int ks = 0; ks < KS_H; ++ks) {
                int buf = ks & 1;
                if (ks + 1 < KS_H) stageB(gW, WH_SS, ks + 1, 128, cc * 32, 2048, buf ^ 1);
                mmaStep(sAhi + ((mt * 16 + ks) * 32 + lane) * 4,
                        sAlo + ((mt * 16 + ks) * 32 + lane) * 4, buf, 16, cg * 16);
                __syncthreads();
            }
            bool w0 = head ? (role0 != 0) : (role0 == 0);
            bool w1 = head ? (role1 != 0) : (role1 == 0);
            #pragma unroll
            for (int nt = 0; nt < 16; ++nt) {
                int c = cc * 256 + cg * 128 + nt * 8 + cb;
                float2 bv = *(const float2*)(bias + c);
                if (w0)
                    *(float2*)(out_logits + (size_t)(row0 + r0) * NC + c) =
                        make_float2(d[nt][0] + bv.x, d[nt][1] + bv.y);
                if (w1)
                    *(float2*)(out_logits + (size_t)(row0 + r1) * NC + c) =
                        make_float2(d[nt][2] + bv.x, d[nt][3] + bv.y);
            }
        }
    }

    // ---- Stage 5: address head ----
    zeroD();
    stageB(g_Wad, WAD_SS, 0, 8, 0, 512, 0);
    __syncthreads();
    for (int ks = 0; ks < KS_H; ++ks) {
        int buf = ks & 1;
        if (ks + 1 < KS_H) stageB(g_Wad, WAD_SS, ks + 1, 8, 0, 512, buf ^ 1);
        mmaStep(sAhi + ((mt * 16 + ks) * 32 + lane) * 4,
                sAlo + ((mt * 16 + ks) * 32 + lane) * 4, buf, 4, cg * 4);
        __syncthreads();
    }
    #pragma unroll
    for (int nt = 0; nt < 4; ++nt) {
        int c = (cg * 4 + nt) * 8 + cb;
        float2 bv = *(const float2*)(bad + c);
        *(float2*)(out_addr + (size_t)(row0 + r0) * AD + c) =
            make_float2(d[nt][0] + bv.x, d[nt][1] + bv.y);
        *(float2*)(out_addr + (size_t)(row0 + r1) * AD + c) =
            make_float2(d[nt][2] + bv.x, d[nt][3] + bv.y);
    }
}

extern "C" void kernel_launch(void* const* d_in, const int* in_sizes, int n_in,
                              void* d_out, int out_size) {
    const float* key   = (const float*)d_in[0];
    const float* aux   = (const float*)d_in[1];
    const float* res   = (const float*)d_in[2];
    const int*   role  = (const int*)  d_in[3];
    const float* Wk  = (const float*)d_in[4];  const float* bk    = (const float*)d_in[5];
    const float* Wa  = (const float*)d_in[6];  const float* ba    = (const float*)d_in[7];
    const float* Wr  = (const float*)d_in[8];  const float* br    = (const float*)d_in[9];
    const float* g_in= (const float*)d_in[10]; const float* b_in  = (const float*)d_in[11];
    const float* Wb0 = (const float*)d_in[12]; const float* bb0   = (const float*)d_in[13];
    const float* g0  = (const float*)d_in[14]; const float* beta0 = (const float*)d_in[15];
    const float* Wb1 = (const float*)d_in[16]; const float* bb1   = (const float*)d_in[17];
    const float* g1  = (const float*)d_in[18]; const float* beta1 = (const float*)d_in[19];
    const float* Ww  = (const float*)d_in[20]; const float* bw    = (const float*)d_in[21];
    const float* Wq  = (const float*)d_in[22]; const float* bq    = (const float*)d_in[23];
    const float* Wad = (const float*)d_in[24]; const float* bad   = (const float*)d_in[25];

    const int N = in_sizes[3];
    float* out = (float*)d_out;

    uint32_t *pWin, *pWb0, *pWb1, *pWw, *pWq, *pWad;
    cudaGetSymbolAddress((void**)&pWin, g_Win);
    cudaGetSymbolAddress((void**)&pWb0, g_Wb0);
    cudaGetSymbolAddress((void**)&pWb1, g_Wb1);
    cudaGetSymbolAddress((void**)&pWw,  g_Ww);
    cudaGetSymbolAddress((void**)&pWq,  g_Wq);
    cudaGetSymbolAddress((void**)&pWad, g_Wad);

    auto blks = [](int K, int Ncols) { return (K * Ncols / 2 + 255) / 256; };
    pack_weight_kernel<<<blks(128, 256), 256>>>(Wk, 128, 256, 1.0f,  pWin, 0,  32, WIN_SS);
    pack_weight_kernel<<<blks(256, 256), 256>>>(Wa, 256, 256, 1.0f,  pWin, 8,  32, WIN_SS);
    pack_weight_kernel<<<blks(256, 256), 256>>>(Wr, 256, 256, 0.1f,  pWin, 24, 32, WIN_SS);
    pack_weight_kernel<<<blks(256, 256), 256>>>(Wb0, 256, 256, 1.0f, pWb0, 0,  32, WB_SS);
    pack_weight_kernel<<<blks(256, 256), 256>>>(Wb1, 256, 256, 1.0f, pWb1, 0,  32, WB_SS);
    pack_weight_kernel<<<blks(256, 1024), 256>>>(Ww, 256, 1024, 1.0f, pWw, 0, 128, WH_SS);
    pack_weight_kernel<<<blks(256, 1024), 256>>>(Wq, 256, 1024, 1.0f, pWq, 0, 128, WH_SS);
    pack_weight_kernel<<<blks(256, 64), 256>>>(Wad, 256, 64, 1.0f,   pWad, 0, 8,  WAD_SS);

    cudaFuncSetAttribute(apsgnn_mma_kernel,
                         cudaFuncAttributeMaxDynamicSharedMemorySize, SMEM_BYTES);
    apsgnn_mma_kernel<<<N / RB, TPB, SMEM_BYTES>>>(
        key, aux, res, role, bk, ba, br, g_in, b_in,
        bb0, g0, beta0, bb1, g1, beta1, bw, bq, bad,
        out, out + (size_t)N * NC, out + (size_t)N * (NC + HD));
}